// round 12
// baseline (speedup 1.0000x reference)
#include <cuda_runtime.h>

// Shapes fixed by reference setup_inputs
#define B_DIM 128
#define N_DIM 1024
#define K_DIM 512            // D*S
#define K_VEC (K_DIM / 4)    // 128 float4 per row
#define ALPHA 0.05f
#define THETA_LR 0.1f
#define R_TARGET 0.1f
#define BPW 4                // batch rows per warp

// Streaming-layout kernel (R1 ordering, W amortized, epilogue fused).
// Evidence: R1's warp-per-(b,n) n-sweep layout hit ~41.7us even while
// LTS-throttled (W re-read 128x from L2); all 2KB-granule fused layouts
// plateau at 6.2-6.4 TB/s. Theory: sequential 16KB-chunk streaming has
// better DRAM locality than 2KB scatter at 2MB stride.
// Block = 8 warps = 8 consecutive neurons at one b-quad: block reads
// x[b][n0:n0+8][:] = 16KB contiguous per b, 4 b's. Grid sweeps n-major
// then b -> chip-wide near-sequential x traversal. W per warp loaded once,
// reused 4x (L2 W traffic 64MB; LTS total ~330MB, below the ~12TB/s cap).
// Rates: device-global counters, self-resetting (validated in R10 run):
// 32 warps per neuron; 32nd arriver finalizes and resets -> deterministic
// under graph replay. Per-row FMA chain + butterfly identical to all
// passing kernels -> spikes bit-identical.

__device__ int g_cnt[N_DIM];   // zero-init at module load; reset each run
__device__ int g_arr[N_DIM];   // zero-init at module load; reset each run

__global__ __launch_bounds__(256) void mpjrd_stream(
    const float4* __restrict__ x,     // [B, N, 128] float4
    const float4* __restrict__ W,     // [N, 128] float4
    const float* __restrict__ theta,  // [N]
    const float* __restrict__ r_hat,  // [N]
    float* __restrict__ spikes,       // [B, N]
    float* __restrict__ rates,        // [N]
    float* __restrict__ thetas,       // [N]
    float* __restrict__ r_hats)       // [N]
{
    const int w    = threadIdx.x >> 5;        // warp 0..7
    const int lane = threadIdx.x & 31;
    const int ng   = blockIdx.x & 127;        // n-group (sweeps fastest)
    const int bq   = blockIdx.x >> 7;         // b-quad 0..31
    const int n    = ng * 8 + w;              // this warp's neuron
    const int b0   = bq * BPW;                // first of 4 batch rows

    // W row into registers, reused for 4 b-rows
    const float4* wr = W + (size_t)n * K_VEC;
    float4 wreg[4];
#pragma unroll
    for (int k = 0; k < 4; k++) wreg[k] = __ldg(&wr[lane + 32 * k]);

    const float th = __ldg(&theta[n]);

    int cnt = 0;

    // 4 rows, 2 at a time (8 LDG.128 in flight); math order identical to R4
#pragma unroll
    for (int i = 0; i < BPW; i += 2) {
        const int ba = b0 + i;
        const int bb = b0 + i + 1;
        const float4* x0 = x + ((size_t)ba * N_DIM + n) * K_VEC;
        const float4* x1 = x + ((size_t)bb * N_DIM + n) * K_VEC;

        float4 a0[4], a1[4];
#pragma unroll
        for (int k = 0; k < 4; k++) a0[k] = __ldcs(&x0[lane + 32 * k]);
#pragma unroll
        for (int k = 0; k < 4; k++) a1[k] = __ldcs(&x1[lane + 32 * k]);

        float acc0 = 0.0f, acc1 = 0.0f;
#pragma unroll
        for (int k = 0; k < 4; k++) {
            acc0 = fmaf(a0[k].x, wreg[k].x, acc0);
            acc0 = fmaf(a0[k].y, wreg[k].y, acc0);
            acc0 = fmaf(a0[k].z, wreg[k].z, acc0);
            acc0 = fmaf(a0[k].w, wreg[k].w, acc0);
            acc1 = fmaf(a1[k].x, wreg[k].x, acc1);
            acc1 = fmaf(a1[k].y, wreg[k].y, acc1);
            acc1 = fmaf(a1[k].z, wreg[k].z, acc1);
            acc1 = fmaf(a1[k].w, wreg[k].w, acc1);
        }

#pragma unroll
        for (int off = 16; off > 0; off >>= 1) {
            acc0 += __shfl_xor_sync(0xFFFFFFFFu, acc0, off);
            acc1 += __shfl_xor_sync(0xFFFFFFFFu, acc1, off);
        }

        if (lane == 0) {
            const float s0 = (acc0 >= th) ? 1.0f : 0.0f;
            const float s1 = (acc1 >= th) ? 1.0f : 0.0f;
            spikes[(size_t)ba * N_DIM + n] = s0;
            spikes[(size_t)bb * N_DIM + n] = s1;
            cnt += (int)s0 + (int)s1;
        }
    }

    // Per-warp arrival; 32nd arriver (B/BPW = 32 warps/neuron) finalizes
    // neuron n and resets counters for the next graph replay.
    if (lane == 0) {
        atomicAdd(&g_cnt[n], cnt);
        __threadfence();                       // count visible before arrival
        const int arr = atomicAdd(&g_arr[n], 1);
        if (arr == (B_DIM / BPW) - 1) {
            __threadfence();                   // acquire all prior counts
            const int total = atomicExch(&g_cnt[n], 0);   // read + reset
            atomicExch(&g_arr[n], 0);                     // reset
            const float rate = (float)total * (1.0f / (float)B_DIM);
            const float rh = (1.0f - ALPHA) * r_hat[n] + ALPHA * rate;
            const float thn = theta[n] + THETA_LR * (rh - R_TARGET);
            rates[n]  = rate;
            r_hats[n] = rh;
            thetas[n] = thn;
        }
    }
}

extern "C" void kernel_launch(void* const* d_in, const int* in_sizes, int n_in,
                              void* d_out, int out_size) {
    const float4* x     = (const float4*)d_in[0];   // [B, N, D, S] f32
    const float4* W     = (const float4*)d_in[1];   // [N, D, S] f32
    const float* theta  = (const float*)d_in[2];    // [N]
    const float* r_hat  = (const float*)d_in[3];    // [N]

    float* out    = (float*)d_out;
    float* spikes = out;                       // [B*N]
    float* rates  = out + B_DIM * N_DIM;       // [N]
    float* thetas = rates + N_DIM;             // [N]
    float* r_hats = thetas + N_DIM;            // [N]

    // (B/BPW) * (N/8) = 32 * 128 = 4096 blocks of 256 threads
    mpjrd_stream<<<(B_DIM / BPW) * (N_DIM / 8), 256>>>(
        x, W, theta, r_hat, spikes, rates, thetas, r_hats);
}

// round 13
// speedup vs baseline: 1.0423x; 1.0423x over previous
#include <cuda_runtime.h>

// Shapes fixed by reference setup_inputs
#define B_DIM 128
#define N_DIM 1024
#define K_DIM 512            // D*S
#define K_VEC (K_DIM / 4)    // 128 float4 per row
#define ALPHA 0.05f
#define THETA_LR 0.1f
#define R_TARGET 0.1f

// Half-batch-per-CTA variant of the best (R4) kernel.
// Evidence: R4/R9 (neuron-per-CTA, strict single wave) pin at 6.4 TB/s /
// ~80% time-averaged DRAM; MLP, occupancy, granularity, and traversal-order
// changes all failed to move it. Remaining gap is ramp + end-of-wave
// straggler: a single pinned wave ends when the slowest SM drains.
// Fix: 2 CTAs per neuron (64 b-rows each), grid 2048 x 128. ~14 CTAs of
// work per SM vs ~8 resident -> ~1.7 rounds, so the HW queue backfills
// freed slots and the tail shrinks at ~7% granularity. Units are 8x
// coarser than the failed R10 experiment: W reuse 16x/warp (L2 W traffic
// 16 MB), 8 atomic arrivals per neuron (vs 32), inner loop byte-identical
// to R4 -> spikes bit-identical.
// Rates: device-global counters, self-resetting via atomicExch (validated
// in R10/R12 runs) -> deterministic under graph replay, no second launch.

__device__ int g_cnt[N_DIM];   // zero-init at module load; self-resetting
__device__ int g_arr[N_DIM];   // zero-init at module load; self-resetting

__global__ __launch_bounds__(128) void mpjrd_half(
    const float4* __restrict__ x,     // [B, N, 128] float4
    const float4* __restrict__ W,     // [N, 128] float4
    const float* __restrict__ theta,  // [N]
    const float* __restrict__ r_hat,  // [N]
    float* __restrict__ spikes,       // [B, N]
    float* __restrict__ rates,        // [N]
    float* __restrict__ thetas,       // [N]
    float* __restrict__ r_hats)       // [N]
{
    const int tid  = threadIdx.x;
    const int w    = tid >> 5;               // warp 0..3
    const int lane = tid & 31;
    const int n    = blockIdx.x >> 1;        // neuron (slow dim, R4-like order)
    const int half = blockIdx.x & 1;         // 0 or 1
    const int bb   = half * 64 + w * 16;     // this warp's 16 batch rows

    // W row into registers: lane covers float4 indices lane, lane+32, +64, +96
    const float4* wr = W + (size_t)n * K_VEC;
    float4 wreg[4];
#pragma unroll
    for (int k = 0; k < 4; k++) wreg[k] = __ldg(&wr[lane + 32 * k]);

    const float th = __ldg(&theta[n]);

    int cnt = 0;

    // 16 rows, 2 at a time (8 LDG.128 in flight); body identical to R4
#pragma unroll 1
    for (int i = 0; i < 16; i += 2) {
        const int b0 = bb + i;
        const int b1 = bb + i + 1;
        const float4* x0 = x + ((size_t)b0 * N_DIM + n) * K_VEC;
        const float4* x1 = x + ((size_t)b1 * N_DIM + n) * K_VEC;

        float4 a0[4], a1[4];
#pragma unroll
        for (int k = 0; k < 4; k++) a0[k] = __ldcs(&x0[lane + 32 * k]);
#pragma unroll
        for (int k = 0; k < 4; k++) a1[k] = __ldcs(&x1[lane + 32 * k]);

        float acc0 = 0.0f, acc1 = 0.0f;
#pragma unroll
        for (int k = 0; k < 4; k++) {
            acc0 = fmaf(a0[k].x, wreg[k].x, acc0);
            acc0 = fmaf(a0[k].y, wreg[k].y, acc0);
            acc0 = fmaf(a0[k].z, wreg[k].z, acc0);
            acc0 = fmaf(a0[k].w, wreg[k].w, acc0);
            acc1 = fmaf(a1[k].x, wreg[k].x, acc1);
            acc1 = fmaf(a1[k].y, wreg[k].y, acc1);
            acc1 = fmaf(a1[k].z, wreg[k].z, acc1);
            acc1 = fmaf(a1[k].w, wreg[k].w, acc1);
        }

#pragma unroll
        for (int off = 16; off > 0; off >>= 1) {
            acc0 += __shfl_xor_sync(0xFFFFFFFFu, acc0, off);
            acc1 += __shfl_xor_sync(0xFFFFFFFFu, acc1, off);
        }

        if (lane == 0) {
            const float s0 = (acc0 >= th) ? 1.0f : 0.0f;
            const float s1 = (acc1 >= th) ? 1.0f : 0.0f;
            spikes[(size_t)b0 * N_DIM + n] = s0;
            spikes[(size_t)b1 * N_DIM + n] = s1;
            cnt += (int)s0 + (int)s1;
        }
    }

    // Per-warp arrival; 8th arriver (2 CTAs x 4 warps) finalizes neuron n
    // and resets both counters for the next graph replay.
    if (lane == 0) {
        atomicAdd(&g_cnt[n], cnt);
        __threadfence();                       // count visible before arrival
        const int arr = atomicAdd(&g_arr[n], 1);
        if (arr == 7) {
            __threadfence();                   // acquire all prior counts
            const int total = atomicExch(&g_cnt[n], 0);   // read + reset
            atomicExch(&g_arr[n], 0);                     // reset
            const float rate = (float)total * (1.0f / (float)B_DIM);
            const float rh = (1.0f - ALPHA) * r_hat[n] + ALPHA * rate;
            const float thn = theta[n] + THETA_LR * (rh - R_TARGET);
            rates[n]  = rate;
            r_hats[n] = rh;
            thetas[n] = thn;
        }
    }
}

extern "C" void kernel_launch(void* const* d_in, const int* in_sizes, int n_in,
                              void* d_out, int out_size) {
    const float4* x     = (const float4*)d_in[0];   // [B, N, D, S] f32
    const float4* W     = (const float4*)d_in[1];   // [N, D, S] f32
    const float* theta  = (const float*)d_in[2];    // [N]
    const float* r_hat  = (const float*)d_in[3];    // [N]

    float* out    = (float*)d_out;
    float* spikes = out;                       // [B*N]
    float* rates  = out + B_DIM * N_DIM;       // [N]
    float* thetas = rates + N_DIM;             // [N]
    float* r_hats = thetas + N_DIM;            // [N]

    mpjrd_half<<<N_DIM * 2, 128>>>(x, W, theta, r_hat,
                                   spikes, rates, thetas, r_hats);
}

// round 15
// speedup vs baseline: 1.1243x; 1.0787x over previous
#include <cuda_runtime.h>

// Shapes fixed by reference setup_inputs
#define B_DIM 128
#define N_DIM 1024
#define K_DIM 512            // D*S
#define K_VEC (K_DIM / 4)    // 128 float4 per row
#define ALPHA 0.05f
#define THETA_LR 0.1f
#define R_TARGET 0.1f

// FINAL FORM (reverted to the best measured kernel, R4).
// Evidence across 8 measurements: single-wave / statically-pinned /
// atomic-free layouts (this one) run 42.9-43.6us at 79-81% DRAM; every
// deviation (deeper MLP pipeline R9: neutral; fine dynamic units R10:
// -2us; sequential traversal R12: -4us; half-batch multi-round R13: -2us)
// was neutral or worse. x is read exactly once (256MB irreducible), W is
// register-resident, and ~6.4TB/s matches the documented HBM channel
// uniformity ceiling minus ramp/drain. This is the roofline for the
// pattern; structure locked.
//
// Grid: 1024 CTAs (one neuron each), block 128 = 4 warps; warp w owns
// b in [w*32, w*32+32). W row loaded once into 16 regs/lane; x streamed
// with __ldcs (zero reuse, evict-first). Full batch per CTA -> rate/
// theta/r_hat finalize in-kernel, no second launch, no atomics.
__global__ __launch_bounds__(128) void mpjrd_fused(
    const float4* __restrict__ x,     // [B, N, 128] float4
    const float4* __restrict__ W,     // [N, 128] float4
    const float* __restrict__ theta,  // [N]
    const float* __restrict__ r_hat,  // [N]
    float* __restrict__ spikes,       // [B, N]
    float* __restrict__ rates,        // [N]
    float* __restrict__ thetas,       // [N]
    float* __restrict__ r_hats)       // [N]
{
    const int tid  = threadIdx.x;
    const int w    = tid >> 5;        // warp 0..3
    const int lane = tid & 31;
    const int n    = blockIdx.x;      // this CTA's neuron
    const int bb   = w * 32;          // first batch row for this warp

    // W row into registers: lane covers float4 indices lane, lane+32, +64, +96
    const float4* wr = W + (size_t)n * K_VEC;
    float4 wreg[4];
#pragma unroll
    for (int k = 0; k < 4; k++) wreg[k] = __ldg(&wr[lane + 32 * k]);

    const float th = __ldg(&theta[n]);

    __shared__ int s_cnt[4];
    int cnt = 0;

    // 32 batch rows per warp, 2 at a time for MLP (8 LDG.128 in flight)
#pragma unroll 1
    for (int i = 0; i < 32; i += 2) {
        const int b0 = bb + i;
        const int b1 = bb + i + 1;
        const float4* x0 = x + ((size_t)b0 * N_DIM + n) * K_VEC;
        const float4* x1 = x + ((size_t)b1 * N_DIM + n) * K_VEC;

        float4 a0[4], a1[4];
#pragma unroll
        for (int k = 0; k < 4; k++) a0[k] = __ldcs(&x0[lane + 32 * k]);
#pragma unroll
        for (int k = 0; k < 4; k++) a1[k] = __ldcs(&x1[lane + 32 * k]);

        float acc0 = 0.0f, acc1 = 0.0f;
#pragma unroll
        for (int k = 0; k < 4; k++) {
            acc0 = fmaf(a0[k].x, wreg[k].x, acc0);
            acc0 = fmaf(a0[k].y, wreg[k].y, acc0);
            acc0 = fmaf(a0[k].z, wreg[k].z, acc0);
            acc0 = fmaf(a0[k].w, wreg[k].w, acc0);
            acc1 = fmaf(a1[k].x, wreg[k].x, acc1);
            acc1 = fmaf(a1[k].y, wreg[k].y, acc1);
            acc1 = fmaf(a1[k].z, wreg[k].z, acc1);
            acc1 = fmaf(a1[k].w, wreg[k].w, acc1);
        }

        // Butterfly reductions (interleaved to hide SHFL latency)
#pragma unroll
        for (int off = 16; off > 0; off >>= 1) {
            acc0 += __shfl_xor_sync(0xFFFFFFFFu, acc0, off);
            acc1 += __shfl_xor_sync(0xFFFFFFFFu, acc1, off);
        }

        if (lane == 0) {
            const float s0 = (acc0 >= th) ? 1.0f : 0.0f;
            const float s1 = (acc1 >= th) ? 1.0f : 0.0f;
            spikes[(size_t)b0 * N_DIM + n] = s0;
            spikes[(size_t)b1 * N_DIM + n] = s1;
            cnt += (int)s0 + (int)s1;
        }
    }

    if (lane == 0) s_cnt[w] = cnt;
    __syncthreads();

    // Thread 0 finalizes neuron n
    if (tid == 0) {
        const int total = s_cnt[0] + s_cnt[1] + s_cnt[2] + s_cnt[3];
        const float rate = (float)total * (1.0f / (float)B_DIM);
        const float rh = (1.0f - ALPHA) * r_hat[n] + ALPHA * rate;
        const float thn = theta[n] + THETA_LR * (rh - R_TARGET);
        rates[n]  = rate;
        r_hats[n] = rh;
        thetas[n] = thn;
    }
}

extern "C" void kernel_launch(void* const* d_in, const int* in_sizes, int n_in,
                              void* d_out, int out_size) {
    const float4* x     = (const float4*)d_in[0];   // [B, N, D, S] f32
    const float4* W     = (const float4*)d_in[1];   // [N, D, S] f32
    const float* theta  = (const float*)d_in[2];    // [N]
    const float* r_hat  = (const float*)d_in[3];    // [N]

    float* out    = (float*)d_out;
    float* spikes = out;                       // [B*N]
    float* rates  = out + B_DIM * N_DIM;       // [N]
    float* thetas = rates + N_DIM;             // [N]
    float* r_hats = thetas + N_DIM;            // [N]

    mpjrd_fused<<<N_DIM, 128>>>(x, W, theta, r_hat,
                                spikes, rates, thetas, r_hats);
}